// round 3
// baseline (speedup 1.0000x reference)
#include <cuda_runtime.h>

// Problem geometry (fixed by the dataset)
#define D_IN 384
#define H_IN 128
#define W_IN 128
#define NVOX (D_IN * H_IN * W_IN)        // 6,291,456 input voxels
#define S0 128
#define S1 128
#define S2 128
#define NOUT (S0 * S1 * S2)              // 2,097,152 per channel
// flow scale = (x.shape[d]-1)/(flow.shape[d]-1) = 1.0 for all dims here.

__global__ void zero_out_kernel(float4* __restrict__ out, int n4) {
    int i = blockIdx.x * blockDim.x + threadIdx.x;
    if (i < n4) out[i] = make_float4(0.f, 0.f, 0.f, 0.f);
}

__global__ __launch_bounds__(256) void splat_kernel(
    const float* __restrict__ x,
    const float* __restrict__ flow,
    const float* __restrict__ mask,
    float* __restrict__ out)
{
    int tid = blockIdx.x * blockDim.x + threadIdx.x;
    if (tid >= NVOX) return;

    int ix = tid & (W_IN - 1);
    int iy = (tid >> 7) & (H_IN - 1);
    int iz = tid >> 14;

    float m  = mask[tid];
    float v0 = x[tid] * m;                 // channel 0: x * mask
    // channel 1: mask (== m)

    float cz = flow[tid]            + (float)iz;
    float cy = flow[tid + NVOX]     + (float)iy;
    float cx = flow[tid + 2 * NVOX] + (float)ix;

    // Per-dimension corner indices + weights, with replicate-clip.
    // When both clipped indices coincide (weights sum to 1 for that dim),
    // merge into a single corner — this halves atomics for the whole
    // z>=129 region that collapses onto the z=127 plane.
    int   zi[2], yi[2], xi[2];
    float zw[2], yw[2], xw[2];
    int nz, ny, nx;

    {
        float f0 = floorf(cz); float t = cz - f0;
        int i0 = (int)f0, i1 = i0 + 1;
        i0 = min(max(i0, 0), S0 - 1);
        i1 = min(max(i1, 0), S0 - 1);
        if (i0 == i1) { nz = 1; zi[0] = i0; zw[0] = 1.f; }
        else { nz = 2; zi[0] = i0; zw[0] = 1.f - t; zi[1] = i1; zw[1] = t; }
    }
    {
        float f0 = floorf(cy); float t = cy - f0;
        int i0 = (int)f0, i1 = i0 + 1;
        i0 = min(max(i0, 0), S1 - 1);
        i1 = min(max(i1, 0), S1 - 1);
        if (i0 == i1) { ny = 1; yi[0] = i0; yw[0] = 1.f; }
        else { ny = 2; yi[0] = i0; yw[0] = 1.f - t; yi[1] = i1; yw[1] = t; }
    }
    {
        float f0 = floorf(cx); float t = cx - f0;
        int i0 = (int)f0, i1 = i0 + 1;
        i0 = min(max(i0, 0), S2 - 1);
        i1 = min(max(i1, 0), S2 - 1);
        if (i0 == i1) { nx = 1; xi[0] = i0; xw[0] = 1.f; }
        else { nx = 2; xi[0] = i0; xw[0] = 1.f - t; xi[1] = i1; xw[1] = t; }
    }

    #pragma unroll 2
    for (int a = 0; a < nz; a++) {
        int   zb  = zi[a] * S1;
        float wz  = zw[a];
        #pragma unroll 2
        for (int b = 0; b < ny; b++) {
            int   yb  = (zb + yi[b]) * S2;
            float wzy = wz * yw[b];
            #pragma unroll 2
            for (int c = 0; c < nx; c++) {
                int   flat = yb + xi[c];
                float w    = wzy * xw[c];
                atomicAdd(out + flat,        v0 * w);  // RED.E.ADD (no return)
                atomicAdd(out + NOUT + flat, m  * w);
            }
        }
    }
}

extern "C" void kernel_launch(void* const* d_in, const int* in_sizes, int n_in,
                              void* d_out, int out_size) {
    const float* x    = (const float*)d_in[0];
    const float* flow = (const float*)d_in[1];
    const float* mask = (const float*)d_in[2];
    float* out = (float*)d_out;

    // Output is poisoned — zero the 2-channel volume first.
    int n4 = (2 * NOUT) / 4;   // 1,048,576 float4
    zero_out_kernel<<<(n4 + 255) / 256, 256>>>((float4*)out, n4);

    splat_kernel<<<(NVOX + 255) / 256, 256>>>(x, flow, mask, out);
}

// round 4
// speedup vs baseline: 1.4952x; 1.4952x over previous
#include <cuda_runtime.h>

// Problem geometry (fixed by the dataset)
#define D_IN 384
#define H_IN 128
#define W_IN 128
#define NVOX (D_IN * H_IN * W_IN)        // 6,291,456 input voxels
#define S0 128
#define S1 128
#define S2 128
#define NOUT (S0 * S1 * S2)              // 2,097,152 per channel
// flow scale = (x.shape[d]-1)/(flow.shape[d]-1) = 1.0 for all dims here.

// Channel-interleaved scratch accumulator: [z][y][x][c], c=2.
// Device global (no dynamic allocation allowed). 16 MB.
__device__ __align__(16) float g_scratch[2 * NOUT];

__global__ void zero_scratch_kernel() {
    int i = blockIdx.x * blockDim.x + threadIdx.x;
    ((float4*)g_scratch)[i] = make_float4(0.f, 0.f, 0.f, 0.f);
}

__device__ __forceinline__ void red_add_v2(float* p, float a, float b) {
    asm volatile("red.global.add.v2.f32 [%0], {%1, %2};"
                 :: "l"(p), "f"(a), "f"(b) : "memory");
}

__global__ __launch_bounds__(256) void splat_kernel(
    const float* __restrict__ x,
    const float* __restrict__ flow,
    const float* __restrict__ mask)
{
    int tid = blockIdx.x * blockDim.x + threadIdx.x;

    int ix = tid & (W_IN - 1);
    int iy = (tid >> 7) & (H_IN - 1);
    int iz = tid >> 14;

    float m  = mask[tid];
    float v0 = x[tid] * m;                 // channel 0: x * mask
    // channel 1: mask (== m)

    float cz = flow[tid]            + (float)iz;
    float cy = flow[tid + NVOX]     + (float)iy;
    float cx = flow[tid + 2 * NVOX] + (float)ix;

    // Per-dimension corner indices + weights, replicate-clip.
    // When both clipped indices coincide, merge into a single corner
    // (halves work for the entire z>=129 region collapsing onto z=127).
    int   zi[2], yi[2], xi[2];
    float zw[2], yw[2], xw[2];
    int nz, ny, nx;

    {
        float f0 = floorf(cz); float t = cz - f0;
        int i0 = (int)f0, i1 = i0 + 1;
        i0 = min(max(i0, 0), S0 - 1);
        i1 = min(max(i1, 0), S0 - 1);
        if (i0 == i1) { nz = 1; zi[0] = i0; zw[0] = 1.f; }
        else { nz = 2; zi[0] = i0; zw[0] = 1.f - t; zi[1] = i1; zw[1] = t; }
    }
    {
        float f0 = floorf(cy); float t = cy - f0;
        int i0 = (int)f0, i1 = i0 + 1;
        i0 = min(max(i0, 0), S1 - 1);
        i1 = min(max(i1, 0), S1 - 1);
        if (i0 == i1) { ny = 1; yi[0] = i0; yw[0] = 1.f; }
        else { ny = 2; yi[0] = i0; yw[0] = 1.f - t; yi[1] = i1; yw[1] = t; }
    }
    {
        float f0 = floorf(cx); float t = cx - f0;
        int i0 = (int)f0, i1 = i0 + 1;
        i0 = min(max(i0, 0), S2 - 1);
        i1 = min(max(i1, 0), S2 - 1);
        if (i0 == i1) { nx = 1; xi[0] = i0; xw[0] = 1.f; }
        else { nx = 2; xi[0] = i0; xw[0] = 1.f - t; xi[1] = i1; xw[1] = t; }
    }

    #pragma unroll 2
    for (int a = 0; a < nz; a++) {
        int   zb  = zi[a] * S1;
        float wz  = zw[a];
        #pragma unroll 2
        for (int b = 0; b < ny; b++) {
            int   yb  = (zb + yi[b]) * S2;
            float wzy = wz * yw[b];
            #pragma unroll 2
            for (int c = 0; c < nx; c++) {
                int   flat = yb + xi[c];
                float w    = wzy * xw[c];
                // One vectorized reduction covers both channels.
                red_add_v2(g_scratch + 2 * flat, v0 * w, m * w);
            }
        }
    }
}

// De-interleave scratch [i][c] -> out[c][i]. Writes every output element,
// so no separate output zeroing is needed.
__global__ void finalize_kernel(float* __restrict__ out) {
    int i = blockIdx.x * blockDim.x + threadIdx.x;   // handles 2 output voxels
    float4 s = ((const float4*)g_scratch)[i];        // (v0[2i], m[2i], v0[2i+1], m[2i+1])
    float2* o0 = (float2*)(out) + i;
    float2* o1 = (float2*)(out + NOUT) + i;
    *o0 = make_float2(s.x, s.z);
    *o1 = make_float2(s.y, s.w);
}

extern "C" void kernel_launch(void* const* d_in, const int* in_sizes, int n_in,
                              void* d_out, int out_size) {
    const float* x    = (const float*)d_in[0];
    const float* flow = (const float*)d_in[1];
    const float* mask = (const float*)d_in[2];
    float* out = (float*)d_out;

    zero_scratch_kernel<<<(2 * NOUT / 4) / 256, 256>>>();
    splat_kernel<<<NVOX / 256, 256>>>(x, flow, mask);
    finalize_kernel<<<(NOUT / 2) / 256, 256>>>(out);
}

// round 6
// speedup vs baseline: 2.4817x; 1.6598x over previous
#include <cuda_runtime.h>

// Problem geometry (fixed by the dataset)
#define D_IN 384
#define H_IN 128
#define W_IN 128
#define NVOX (D_IN * H_IN * W_IN)        // 6,291,456 input voxels
#define S0 128
#define S1 128
#define S2 128
#define NOUT (S0 * S1 * S2)              // 2,097,152 per channel
// flow scale = (x.shape[d]-1)/(flow.shape[d]-1) = 1.0 for all dims here.

// Channel-interleaved scratch accumulators: [z][y][x][c], c=2 (8 bytes per voxel).
// A receives even-xi corner pairs (16B-aligned at 2*flat).
// B receives odd-xi corner pairs; its effective base is g_B+2 floats (8-byte
// offset), so odd-flat pair addresses are 16B-aligned there.
__device__ __align__(16) float g_A[2 * NOUT];
__device__ __align__(16) float g_B[2 * NOUT + 4];

__global__ void zero_scratch_kernel() {
    int i = blockIdx.x * blockDim.x + threadIdx.x;
    const int nA4 = (2 * NOUT) / 4;            // 1,048,576
    const int nB4 = (2 * NOUT + 4) / 4;        // 1,048,577
    if (i < nA4) ((float4*)g_A)[i] = make_float4(0.f, 0.f, 0.f, 0.f);
    if (i < nB4) ((float4*)g_B)[i] = make_float4(0.f, 0.f, 0.f, 0.f);
}

__device__ __forceinline__ void red_add_v2(float* p, float a, float b) {
    asm volatile("red.global.add.v2.f32 [%0], {%1, %2};"
                 :: "l"(p), "f"(a), "f"(b) : "memory");
}
__device__ __forceinline__ void red_add_v4(float* p, float a, float b, float c, float d) {
    asm volatile("red.global.add.v4.f32 [%0], {%1, %2, %3, %4};"
                 :: "l"(p), "f"(a), "f"(b), "f"(c), "f"(d) : "memory");
}

__global__ __launch_bounds__(256) void splat_kernel(
    const float* __restrict__ x,
    const float* __restrict__ flow,
    const float* __restrict__ mask)
{
    int tid = blockIdx.x * blockDim.x + threadIdx.x;

    int ix = tid & (W_IN - 1);
    int iy = (tid >> 7) & (H_IN - 1);
    int iz = tid >> 14;

    float m  = mask[tid];
    float v0 = x[tid] * m;                 // channel 0: x * mask
    // channel 1: mask (== m)

    float cz = flow[tid]            + (float)iz;
    float cy = flow[tid + NVOX]     + (float)iy;
    float cx = flow[tid + 2 * NVOX] + (float)ix;

    // Per-dimension corner indices + weights, replicate-clip.
    // When both clipped indices coincide, merge into a single corner
    // (halves work for the entire z>=129 region collapsing onto z=127).
    int   zi[2], yi[2];
    float zw[2], yw[2];
    int nz, ny;

    {
        float f0 = floorf(cz); float t = cz - f0;
        int i0 = (int)f0, i1 = i0 + 1;
        i0 = min(max(i0, 0), S0 - 1);
        i1 = min(max(i1, 0), S0 - 1);
        if (i0 == i1) { nz = 1; zi[0] = i0; zw[0] = 1.f; }
        else { nz = 2; zi[0] = i0; zw[0] = 1.f - t; zi[1] = i1; zw[1] = t; }
    }
    {
        float f0 = floorf(cy); float t = cy - f0;
        int i0 = (int)f0, i1 = i0 + 1;
        i0 = min(max(i0, 0), S1 - 1);
        i1 = min(max(i1, 0), S1 - 1);
        if (i0 == i1) { ny = 1; yi[0] = i0; yw[0] = 1.f; }
        else { ny = 2; yi[0] = i0; yw[0] = 1.f - t; yi[1] = i1; yw[1] = t; }
    }

    // x dimension: keep pair structure for the vectorized RED.
    int   xi0;            // left corner (only valid corner when nxp == 1)
    float xw0, xw1;       // weights for xi0, xi0+1
    int   nxp;            // 1 = single clipped corner, 2 = pair
    {
        float f0 = floorf(cx); float t = cx - f0;
        int i0 = (int)f0, i1 = i0 + 1;
        i0 = min(max(i0, 0), S2 - 1);
        i1 = min(max(i1, 0), S2 - 1);
        if (i0 == i1) { nxp = 1; xi0 = i0; xw0 = 1.f; xw1 = 0.f; }
        else { nxp = 2; xi0 = i0; xw0 = 1.f - t; xw1 = t; }
    }

    // Pair buffer: even xi0 -> A, odd xi0 -> B (8-byte-offset base => aligned).
    float* pair_buf = (xi0 & 1) ? (g_B + 2) : g_A;

    #pragma unroll 2
    for (int a = 0; a < nz; a++) {
        int   zb  = zi[a] * S1;
        float wz  = zw[a];
        #pragma unroll 2
        for (int b = 0; b < ny; b++) {
            int   flat = (zb + yi[b]) * S2 + xi0;
            float wzy  = wz * yw[b];
            if (nxp == 2) {
                // One 16B reduction: both x-corners x both channels.
                float wa = wzy * xw0, wb = wzy * xw1;
                red_add_v4(pair_buf + 2 * flat, v0 * wa, m * wa, v0 * wb, m * wb);
            } else {
                red_add_v2(g_A + 2 * flat, v0 * wzy, m * wzy);
            }
        }
    }
}

// out[c][i] = A[i][c] + B[i][c]; writes every output element (no out zeroing).
__global__ void finalize_kernel(float* __restrict__ out) {
    int i = blockIdx.x * blockDim.x + threadIdx.x;   // handles 2 output voxels
    float4 a = ((const float4*)g_A)[i];
    const float2* Bv = (const float2*)(g_B + 2);
    float2 b0 = Bv[2 * i];
    float2 b1 = Bv[2 * i + 1];
    float2* o0 = (float2*)(out) + i;
    float2* o1 = (float2*)(out + NOUT) + i;
    *o0 = make_float2(a.x + b0.x, a.z + b1.x);
    *o1 = make_float2(a.y + b0.y, a.w + b1.y);
}

extern "C" void kernel_launch(void* const* d_in, const int* in_sizes, int n_in,
                              void* d_out, int out_size) {
    const float* x    = (const float*)d_in[0];
    const float* flow = (const float*)d_in[1];
    const float* mask = (const float*)d_in[2];
    float* out = (float*)d_out;

    const int nZero = (2 * NOUT + 4) / 4;   // covers both buffers
    zero_scratch_kernel<<<(nZero + 255) / 256, 256>>>();
    splat_kernel<<<NVOX / 256, 256>>>(x, flow, mask);
    finalize_kernel<<<(NOUT / 2) / 256, 256>>>(out);
}

// round 8
// speedup vs baseline: 2.5033x; 1.0087x over previous
#include <cuda_runtime.h>

// Problem geometry (fixed by the dataset)
#define D_IN 384
#define H_IN 128
#define W_IN 128
#define NVOX (D_IN * H_IN * W_IN)        // 6,291,456 input voxels
#define S0 128
#define S1 128
#define S2 128
#define NOUT (S0 * S1 * S2)              // 2,097,152 per channel
// flow scale = (x.shape[d]-1)/(flow.shape[d]-1) = 1.0 for all dims here.

// Channel-interleaved scratch accumulators: [z][y][x][c], c=2 (8 bytes/voxel).
// A receives even-xi corner pairs (16B-aligned at 2*flat).
// B receives odd-xi corner pairs; effective base g_B+2 floats (8B offset), so
// odd-flat pair addresses are 16B-aligned there. Padded to float4 multiple.
__device__ __align__(16) float g_A[2 * NOUT];
__device__ __align__(16) float g_B[2 * NOUT + 8];

// Exact-cover zeroing: 2048 blocks x 256 threads, 2 float4 per thread per
// buffer, no branches on the hot path.
__global__ __launch_bounds__(256) void zero_scratch_kernel() {
    int i = blockIdx.x * blockDim.x + threadIdx.x;       // 0 .. 524287
    float4 z4 = make_float4(0.f, 0.f, 0.f, 0.f);
    float4* A4 = (float4*)g_A;                           // 1,048,576 entries
    float4* B4 = (float4*)g_B;                           // 1,048,578 entries
    A4[i]          = z4;
    A4[i + 524288] = z4;
    B4[i]          = z4;
    B4[i + 524288] = z4;
    if (i < 2) B4[1048576 + i] = z4;
}

__device__ __forceinline__ void red_add_v2(float* p, float a, float b) {
    asm volatile("red.global.add.v2.f32 [%0], {%1, %2};"
                 :: "l"(p), "f"(a), "f"(b) : "memory");
}
__device__ __forceinline__ void red_add_v4(float* p, float a, float b, float c, float d) {
    asm volatile("red.global.add.v4.f32 [%0], {%1, %2, %3, %4};"
                 :: "l"(p), "f"(a), "f"(b), "f"(c), "f"(d) : "memory");
}

__global__ __launch_bounds__(256) void splat_kernel(
    const float* __restrict__ x,
    const float* __restrict__ flow,
    const float* __restrict__ mask)
{
    int tid = blockIdx.x * blockDim.x + threadIdx.x;

    int ix = tid & (W_IN - 1);
    int iy = (tid >> 7) & (H_IN - 1);
    int iz = tid >> 14;

    float m  = __ldg(mask + tid);
    float v0 = __ldg(x + tid) * m;         // channel 0: x * mask
    // channel 1: mask (== m)

    float cz = __ldg(flow + tid)            + (float)iz;
    float cy = __ldg(flow + tid + NVOX)     + (float)iy;
    float cx = __ldg(flow + tid + 2 * NVOX) + (float)ix;

    // z corners (replicate clip; merged when both clip to the same plane).
    int z0, z1; float wz0, wz1; bool two_z;
    {
        float f0 = floorf(cz); float t = cz - f0;
        int i0 = (int)f0;
        z0 = min(max(i0, 0), S0 - 1);
        z1 = min(max(i0 + 1, 0), S0 - 1);
        two_z = (z0 != z1);
        wz0 = two_z ? (1.f - t) : 1.f;
        wz1 = t;
    }
    // y corners
    int y0, y1; float wy0, wy1; bool two_y;
    {
        float f0 = floorf(cy); float t = cy - f0;
        int i0 = (int)f0;
        y0 = min(max(i0, 0), S1 - 1);
        y1 = min(max(i0 + 1, 0), S1 - 1);
        two_y = (y0 != y1);
        wy0 = two_y ? (1.f - t) : 1.f;
        wy1 = t;
    }
    // x corners (pair kept contiguous for the vectorized RED)
    int xi0; float wx0, wx1; bool two_x;
    {
        float f0 = floorf(cx); float t = cx - f0;
        int i0 = (int)f0;
        int c0 = min(max(i0, 0), S2 - 1);
        int c1 = min(max(i0 + 1, 0), S2 - 1);
        two_x = (c0 != c1);
        xi0 = c0;
        wx0 = two_x ? (1.f - t) : 1.f;
        wx1 = t;
    }

    // Pair buffer: even xi0 -> A, odd xi0 -> B (offset base => 16B aligned).
    float* pair_buf = (xi0 & 1) ? (g_B + 2) : g_A;

    int base0 = (z0 * S1 + y0) * S2 + xi0;     // (z0, y0)
    if (two_x) {
        float w00 = wz0 * wy0;
        red_add_v4(pair_buf + 2 * base0,
                   v0 * (w00 * wx0), m * (w00 * wx0),
                   v0 * (w00 * wx1), m * (w00 * wx1));
        if (two_y) {
            int b01 = (z0 * S1 + y1) * S2 + xi0;
            float w01 = wz0 * wy1;
            red_add_v4(pair_buf + 2 * b01,
                       v0 * (w01 * wx0), m * (w01 * wx0),
                       v0 * (w01 * wx1), m * (w01 * wx1));
        }
        if (two_z) {
            int b10 = (z1 * S1 + y0) * S2 + xi0;
            float w10 = wz1 * wy0;
            red_add_v4(pair_buf + 2 * b10,
                       v0 * (w10 * wx0), m * (w10 * wx0),
                       v0 * (w10 * wx1), m * (w10 * wx1));
            if (two_y) {
                int b11 = (z1 * S1 + y1) * S2 + xi0;
                float w11 = wz1 * wy1;
                red_add_v4(pair_buf + 2 * b11,
                           v0 * (w11 * wx0), m * (w11 * wx0),
                           v0 * (w11 * wx1), m * (w11 * wx1));
            }
        }
    } else {
        float w00 = wz0 * wy0;
        red_add_v2(g_A + 2 * base0, v0 * w00, m * w00);
        if (two_y) {
            int b01 = (z0 * S1 + y1) * S2 + xi0;
            float w01 = wz0 * wy1;
            red_add_v2(g_A + 2 * b01, v0 * w01, m * w01);
        }
        if (two_z) {
            int b10 = (z1 * S1 + y0) * S2 + xi0;
            float w10 = wz1 * wy0;
            red_add_v2(g_A + 2 * b10, v0 * w10, m * w10);
            if (two_y) {
                int b11 = (z1 * S1 + y1) * S2 + xi0;
                float w11 = wz1 * wy1;
                red_add_v2(g_A + 2 * b11, v0 * w11, m * w11);
            }
        }
    }
}

// out[c][i] = A[i][c] + B[i][c]; 4 voxels per thread, float4 stores.
// Writes every output element, so no separate output zeroing is needed.
__global__ __launch_bounds__(256) void finalize_kernel(float* __restrict__ out) {
    int i = blockIdx.x * blockDim.x + threadIdx.x;   // 4 output voxels each
    const float4* A4 = (const float4*)g_A;
    float4 a0 = A4[2 * i];                           // voxels 4i, 4i+1
    float4 a1 = A4[2 * i + 1];                       // voxels 4i+2, 4i+3
    const float2* Bv = (const float2*)(g_B + 2);
    float2 b0 = Bv[4 * i];
    float2 b1 = Bv[4 * i + 1];
    float2 b2 = Bv[4 * i + 2];
    float2 b3 = Bv[4 * i + 3];
    float4* o0 = (float4*)(out) + i;
    float4* o1 = (float4*)(out + NOUT) + i;
    *o0 = make_float4(a0.x + b0.x, a0.z + b1.x, a1.x + b2.x, a1.z + b3.x);
    *o1 = make_float4(a0.y + b0.y, a0.w + b1.y, a1.y + b2.y, a1.w + b3.y);
}

extern "C" void kernel_launch(void* const* d_in, const int* in_sizes, int n_in,
                              void* d_out, int out_size) {
    const float* x    = (const float*)d_in[0];
    const float* flow = (const float*)d_in[1];
    const float* mask = (const float*)d_in[2];
    float* out = (float*)d_out;

    zero_scratch_kernel<<<2048, 256>>>();
    splat_kernel<<<NVOX / 256, 256>>>(x, flow, mask);
    finalize_kernel<<<(NOUT / 4) / 256, 256>>>(out);
}

// round 9
// speedup vs baseline: 2.5276x; 1.0097x over previous
#include <cuda_runtime.h>

// Problem geometry (fixed by the dataset)
#define D_IN 384
#define H_IN 128
#define W_IN 128
#define NVOX (D_IN * H_IN * W_IN)        // 6,291,456 input voxels
#define S0 128
#define S1 128
#define S2 128
#define NOUT (S0 * S1 * S2)              // 2,097,152 per channel
// flow scale = (x.shape[d]-1)/(flow.shape[d]-1) = 1.0 for all dims here.

// Channel-interleaved scratch accumulators: [z][y][x][c], c=2 (8 bytes/voxel).
// A receives even-xi corner pairs (16B-aligned at 2*flat).
// B receives odd-xi corner pairs; effective base g_B+2 floats (8B offset), so
// odd-flat pair addresses are 16B-aligned there.
//
// ZERO INVARIANT: these are zero-initialized at module load (CUDA guarantees
// zero-init of __device__ globals). finalize_kernel restores every byte it
// reads back to zero, so every kernel_launch call — first and replayed —
// begins with zeroed scratch. No separate zeroing kernel is needed.
__device__ __align__(16) float g_A[2 * NOUT];
__device__ __align__(16) float g_B[2 * NOUT + 8];

__device__ __forceinline__ void red_add_v2(float* p, float a, float b) {
    asm volatile("red.global.add.v2.f32 [%0], {%1, %2};"
                 :: "l"(p), "f"(a), "f"(b) : "memory");
}
__device__ __forceinline__ void red_add_v4(float* p, float a, float b, float c, float d) {
    asm volatile("red.global.add.v4.f32 [%0], {%1, %2, %3, %4};"
                 :: "l"(p), "f"(a), "f"(b), "f"(c), "f"(d) : "memory");
}

__global__ __launch_bounds__(256) void splat_kernel(
    const float* __restrict__ x,
    const float* __restrict__ flow,
    const float* __restrict__ mask)
{
    int tid = blockIdx.x * blockDim.x + threadIdx.x;

    int ix = tid & (W_IN - 1);
    int iy = (tid >> 7) & (H_IN - 1);
    int iz = tid >> 14;

    float m  = __ldg(mask + tid);
    float v0 = __ldg(x + tid) * m;         // channel 0: x * mask
    // channel 1: mask (== m)

    float cz = __ldg(flow + tid)            + (float)iz;
    float cy = __ldg(flow + tid + NVOX)     + (float)iy;
    float cx = __ldg(flow + tid + 2 * NVOX) + (float)ix;

    // z corners (replicate clip; merged when both clip to the same plane).
    int z0, z1; float wz0, wz1; bool two_z;
    {
        float f0 = floorf(cz); float t = cz - f0;
        int i0 = (int)f0;
        z0 = min(max(i0, 0), S0 - 1);
        z1 = min(max(i0 + 1, 0), S0 - 1);
        two_z = (z0 != z1);
        wz0 = two_z ? (1.f - t) : 1.f;
        wz1 = t;
    }
    // y corners
    int y0, y1; float wy0, wy1; bool two_y;
    {
        float f0 = floorf(cy); float t = cy - f0;
        int i0 = (int)f0;
        y0 = min(max(i0, 0), S1 - 1);
        y1 = min(max(i0 + 1, 0), S1 - 1);
        two_y = (y0 != y1);
        wy0 = two_y ? (1.f - t) : 1.f;
        wy1 = t;
    }
    // x corners (pair kept contiguous for the vectorized RED)
    int xi0; float wx0, wx1; bool two_x;
    {
        float f0 = floorf(cx); float t = cx - f0;
        int i0 = (int)f0;
        int c0 = min(max(i0, 0), S2 - 1);
        int c1 = min(max(i0 + 1, 0), S2 - 1);
        two_x = (c0 != c1);
        xi0 = c0;
        wx0 = two_x ? (1.f - t) : 1.f;
        wx1 = t;
    }

    // Pair buffer: even xi0 -> A, odd xi0 -> B (offset base => 16B aligned).
    float* pair_buf = (xi0 & 1) ? (g_B + 2) : g_A;

    int base0 = (z0 * S1 + y0) * S2 + xi0;     // (z0, y0)
    if (two_x) {
        float w00 = wz0 * wy0;
        red_add_v4(pair_buf + 2 * base0,
                   v0 * (w00 * wx0), m * (w00 * wx0),
                   v0 * (w00 * wx1), m * (w00 * wx1));
        if (two_y) {
            int b01 = (z0 * S1 + y1) * S2 + xi0;
            float w01 = wz0 * wy1;
            red_add_v4(pair_buf + 2 * b01,
                       v0 * (w01 * wx0), m * (w01 * wx0),
                       v0 * (w01 * wx1), m * (w01 * wx1));
        }
        if (two_z) {
            int b10 = (z1 * S1 + y0) * S2 + xi0;
            float w10 = wz1 * wy0;
            red_add_v4(pair_buf + 2 * b10,
                       v0 * (w10 * wx0), m * (w10 * wx0),
                       v0 * (w10 * wx1), m * (w10 * wx1));
            if (two_y) {
                int b11 = (z1 * S1 + y1) * S2 + xi0;
                float w11 = wz1 * wy1;
                red_add_v4(pair_buf + 2 * b11,
                           v0 * (w11 * wx0), m * (w11 * wx0),
                           v0 * (w11 * wx1), m * (w11 * wx1));
            }
        }
    } else {
        float w00 = wz0 * wy0;
        red_add_v2(g_A + 2 * base0, v0 * w00, m * w00);
        if (two_y) {
            int b01 = (z0 * S1 + y1) * S2 + xi0;
            float w01 = wz0 * wy1;
            red_add_v2(g_A + 2 * b01, v0 * w01, m * w01);
        }
        if (two_z) {
            int b10 = (z1 * S1 + y0) * S2 + xi0;
            float w10 = wz1 * wy0;
            red_add_v2(g_A + 2 * b10, v0 * w10, m * w10);
            if (two_y) {
                int b11 = (z1 * S1 + y1) * S2 + xi0;
                float w11 = wz1 * wy1;
                red_add_v2(g_A + 2 * b11, v0 * w11, m * w11);
            }
        }
    }
}

// out[c][i] = A[i][c] + B[i][c]; 4 voxels per thread, float4 stores.
// Also restores the zero invariant: every scratch address this thread reads
// is written back to zero (same-thread RAW only — B is re-zeroed with the
// exact same 8B-aligned float2 granules it loads, so no cross-thread overlap).
__global__ __launch_bounds__(256) void finalize_kernel(float* __restrict__ out) {
    int i = blockIdx.x * blockDim.x + threadIdx.x;   // 4 output voxels each
    float4* A4 = (float4*)g_A;
    float4 a0 = A4[2 * i];                           // voxels 4i, 4i+1
    float4 a1 = A4[2 * i + 1];                       // voxels 4i+2, 4i+3
    float2* Bv = (float2*)(g_B + 2);
    float2 b0 = Bv[4 * i];
    float2 b1 = Bv[4 * i + 1];
    float2 b2 = Bv[4 * i + 2];
    float2 b3 = Bv[4 * i + 3];

    float4* o0 = (float4*)(out) + i;
    float4* o1 = (float4*)(out + NOUT) + i;
    *o0 = make_float4(a0.x + b0.x, a0.z + b1.x, a1.x + b2.x, a1.z + b3.x);
    *o1 = make_float4(a0.y + b0.y, a0.w + b1.y, a1.y + b2.y, a1.w + b3.y);

    // Restore zeros for the next kernel_launch call / graph replay.
    float4 z4 = make_float4(0.f, 0.f, 0.f, 0.f);
    float2 z2 = make_float2(0.f, 0.f);
    A4[2 * i]     = z4;
    A4[2 * i + 1] = z4;
    Bv[4 * i]     = z2;
    Bv[4 * i + 1] = z2;
    Bv[4 * i + 2] = z2;
    Bv[4 * i + 3] = z2;
}

extern "C" void kernel_launch(void* const* d_in, const int* in_sizes, int n_in,
                              void* d_out, int out_size) {
    const float* x    = (const float*)d_in[0];
    const float* flow = (const float*)d_in[1];
    const float* mask = (const float*)d_in[2];
    float* out = (float*)d_out;

    splat_kernel<<<NVOX / 256, 256>>>(x, flow, mask);
    finalize_kernel<<<(NOUT / 4) / 256, 256>>>(out);
}

// round 10
// speedup vs baseline: 2.6206x; 1.0368x over previous
#include <cuda_runtime.h>

// Problem geometry (fixed by the dataset)
#define D_IN 384
#define H_IN 128
#define W_IN 128
#define NVOX (D_IN * H_IN * W_IN)        // 6,291,456 input voxels
#define S0 128
#define S1 128
#define S2 128
#define NOUT (S0 * S1 * S2)              // 2,097,152 per channel
// flow scale = (x.shape[d]-1)/(flow.shape[d]-1) = 1.0 for all dims here.

// Channel-interleaved scratch accumulators: [z][y][x][c], c=2 (8 bytes/voxel).
// A receives even-xi corner pairs (16B-aligned at 2*flat).
// B receives odd-xi corner pairs; effective base g_B+2 floats (8B offset), so
// odd-flat pair addresses are 16B-aligned there.
//
// ZERO INVARIANT: zero-initialized at module load (CUDA guarantees zero-init
// of __device__ globals). finalize_kernel restores every byte it reads back
// to zero, so every kernel_launch call — first and replayed — begins with
// zeroed scratch. No separate zeroing kernel is needed.
__device__ __align__(16) float g_A[2 * NOUT];
__device__ __align__(16) float g_B[2 * NOUT + 8];

__device__ __forceinline__ void red_add_v2(float* p, float a, float b) {
    asm volatile("red.global.add.v2.f32 [%0], {%1, %2};"
                 :: "l"(p), "f"(a), "f"(b) : "memory");
}
__device__ __forceinline__ void red_add_v4(float* p, float a, float b, float c, float d) {
    asm volatile("red.global.add.v4.f32 [%0], {%1, %2, %3, %4};"
                 :: "l"(p), "f"(a), "f"(b), "f"(c), "f"(d) : "memory");
}
// Streaming (evict-first) load: read-once input must not evict hot scratch
// lines from L2.
__device__ __forceinline__ float ldcs(const float* p) {
    float v;
    asm volatile("ld.global.cs.f32 %0, [%1];" : "=f"(v) : "l"(p));
    return v;
}

__global__ __launch_bounds__(256, 6) void splat_kernel(
    const float* __restrict__ x,
    const float* __restrict__ flow,
    const float* __restrict__ mask)
{
    int tid = blockIdx.x * blockDim.x + threadIdx.x;

    int ix = tid & (W_IN - 1);
    int iy = (tid >> 7) & (H_IN - 1);
    int iz = tid >> 14;

    // Issue all 5 independent input loads up front (streaming policy).
    float m  = ldcs(mask + tid);
    float xv = ldcs(x + tid);
    float fz = ldcs(flow + tid);
    float fy = ldcs(flow + tid + NVOX);
    float fx = ldcs(flow + tid + 2 * NVOX);

    float v0 = xv * m;                    // channel 0: x * mask
    // channel 1: mask (== m)

    float cz = fz + (float)iz;
    float cy = fy + (float)iy;
    float cx = fx + (float)ix;

    // z corners (replicate clip; merged when both clip to the same plane).
    int z0, z1; float wz0, wz1; bool two_z;
    {
        float f0 = floorf(cz); float t = cz - f0;
        int i0 = (int)f0;
        z0 = min(max(i0, 0), S0 - 1);
        z1 = min(max(i0 + 1, 0), S0 - 1);
        two_z = (z0 != z1);
        wz0 = two_z ? (1.f - t) : 1.f;
        wz1 = t;
    }
    // y corners
    int y0, y1; float wy0, wy1; bool two_y;
    {
        float f0 = floorf(cy); float t = cy - f0;
        int i0 = (int)f0;
        y0 = min(max(i0, 0), S1 - 1);
        y1 = min(max(i0 + 1, 0), S1 - 1);
        two_y = (y0 != y1);
        wy0 = two_y ? (1.f - t) : 1.f;
        wy1 = t;
    }
    // x corners (pair kept contiguous for the vectorized RED)
    int xi0; float wx0, wx1; bool two_x;
    {
        float f0 = floorf(cx); float t = cx - f0;
        int i0 = (int)f0;
        int c0 = min(max(i0, 0), S2 - 1);
        int c1 = min(max(i0 + 1, 0), S2 - 1);
        two_x = (c0 != c1);
        xi0 = c0;
        wx0 = two_x ? (1.f - t) : 1.f;
        wx1 = t;
    }

    // Pair buffer: even xi0 -> A, odd xi0 -> B (offset base => 16B aligned).
    float* pair_buf = (xi0 & 1) ? (g_B + 2) : g_A;

    int base0 = (z0 * S1 + y0) * S2 + xi0;     // (z0, y0)
    if (two_x) {
        float w00 = wz0 * wy0;
        red_add_v4(pair_buf + 2 * base0,
                   v0 * (w00 * wx0), m * (w00 * wx0),
                   v0 * (w00 * wx1), m * (w00 * wx1));
        if (two_y) {
            int b01 = (z0 * S1 + y1) * S2 + xi0;
            float w01 = wz0 * wy1;
            red_add_v4(pair_buf + 2 * b01,
                       v0 * (w01 * wx0), m * (w01 * wx0),
                       v0 * (w01 * wx1), m * (w01 * wx1));
        }
        if (two_z) {
            int b10 = (z1 * S1 + y0) * S2 + xi0;
            float w10 = wz1 * wy0;
            red_add_v4(pair_buf + 2 * b10,
                       v0 * (w10 * wx0), m * (w10 * wx0),
                       v0 * (w10 * wx1), m * (w10 * wx1));
            if (two_y) {
                int b11 = (z1 * S1 + y1) * S2 + xi0;
                float w11 = wz1 * wy1;
                red_add_v4(pair_buf + 2 * b11,
                           v0 * (w11 * wx0), m * (w11 * wx0),
                           v0 * (w11 * wx1), m * (w11 * wx1));
            }
        }
    } else {
        float w00 = wz0 * wy0;
        red_add_v2(g_A + 2 * base0, v0 * w00, m * w00);
        if (two_y) {
            int b01 = (z0 * S1 + y1) * S2 + xi0;
            float w01 = wz0 * wy1;
            red_add_v2(g_A + 2 * b01, v0 * w01, m * w01);
        }
        if (two_z) {
            int b10 = (z1 * S1 + y0) * S2 + xi0;
            float w10 = wz1 * wy0;
            red_add_v2(g_A + 2 * b10, v0 * w10, m * w10);
            if (two_y) {
                int b11 = (z1 * S1 + y1) * S2 + xi0;
                float w11 = wz1 * wy1;
                red_add_v2(g_A + 2 * b11, v0 * w11, m * w11);
            }
        }
    }
}

// out[c][i] = A[i][c] + B[i][c]; 4 voxels per thread, float4 stores.
// Also restores the zero invariant: every scratch address this thread reads
// is written back to zero (same-thread RAW only — B is re-zeroed with the
// exact same 8B-aligned float2 granules it loads, so no cross-thread overlap).
__global__ __launch_bounds__(256) void finalize_kernel(float* __restrict__ out) {
    int i = blockIdx.x * blockDim.x + threadIdx.x;   // 4 output voxels each
    float4* A4 = (float4*)g_A;
    float4 a0 = A4[2 * i];                           // voxels 4i, 4i+1
    float4 a1 = A4[2 * i + 1];                       // voxels 4i+2, 4i+3
    float2* Bv = (float2*)(g_B + 2);
    float2 b0 = Bv[4 * i];
    float2 b1 = Bv[4 * i + 1];
    float2 b2 = Bv[4 * i + 2];
    float2 b3 = Bv[4 * i + 3];

    float4* o0 = (float4*)(out) + i;
    float4* o1 = (float4*)(out + NOUT) + i;
    *o0 = make_float4(a0.x + b0.x, a0.z + b1.x, a1.x + b2.x, a1.z + b3.x);
    *o1 = make_float4(a0.y + b0.y, a0.w + b1.y, a1.y + b2.y, a1.w + b3.y);

    // Restore zeros for the next kernel_launch call / graph replay.
    float4 z4 = make_float4(0.f, 0.f, 0.f, 0.f);
    float2 z2 = make_float2(0.f, 0.f);
    A4[2 * i]     = z4;
    A4[2 * i + 1] = z4;
    Bv[4 * i]     = z2;
    Bv[4 * i + 1] = z2;
    Bv[4 * i + 2] = z2;
    Bv[4 * i + 3] = z2;
}

extern "C" void kernel_launch(void* const* d_in, const int* in_sizes, int n_in,
                              void* d_out, int out_size) {
    const float* x    = (const float*)d_in[0];
    const float* flow = (const float*)d_in[1];
    const float* mask = (const float*)d_in[2];
    float* out = (float*)d_out;

    splat_kernel<<<NVOX / 256, 256>>>(x, flow, mask);
    finalize_kernel<<<(NOUT / 4) / 256, 256>>>(out);
}